// round 2
// baseline (speedup 1.0000x reference)
#include <cuda_runtime.h>
#include <cuda_bf16.h>
#include <math.h>

#define RES    2048
#define EMBED  256
#define TLEN   512
#define BATCH  4
#define NTOK   (BATCH*TLEN)
#define SQV    225
#define NHEAD2 450
#define VOCAB  50257
#define NCTA_REC 128
#define ROWS_REC 16

static const size_t LOGITS_N = (size_t)NTOK * VOCAB;

__device__ float    g_Wc[RES * EMBED];
__device__ float    g_xin[(size_t)NTOK * RES];
__device__ float    g_states_tb[(size_t)TLEN * BATCH * RES];
__device__ float    g_states_bt[(size_t)NTOK * RES];
__device__ float    g_L[(size_t)NTOK * NHEAD2];
__device__ float    g_Whcat[NHEAD2 * RES];
__device__ unsigned g_cnt[TLEN];
__device__ float    g_loss_acc;
__device__ int      g_mask_cnt;

__device__ __forceinline__ unsigned ld_acq(const unsigned* p) {
    unsigned v;
    asm volatile("ld.acquire.gpu.u32 %0, [%1];" : "=r"(v) : "l"(p) : "memory");
    return v;
}

__global__ void prep_kernel(const float* __restrict__ Wh1, const float* __restrict__ Wh2) {
    int i0 = blockIdx.x * blockDim.x + threadIdx.x;
    int stride = gridDim.x * blockDim.x;
    for (int j = i0; j < NHEAD2 * RES; j += stride) {
        int v = j / RES, r = j - v * RES;
        g_Whcat[j] = (v < SQV) ? Wh1[v * RES + r] : Wh2[(v - SQV) * RES + r];
    }
    if (i0 < TLEN) g_cnt[i0] = 0u;
    if (i0 == 0) { g_loss_acc = 0.f; g_mask_cnt = 0; }
}

// Wc = W_ih[2048x2048] @ W_in[2048x256]   (NN GEMM)
__global__ __launch_bounds__(256) void gemm_nn_wc(const float* __restrict__ A,
                                                  const float* __restrict__ B) {
    const int N = EMBED, K = RES;
    __shared__ float As[16][68];
    __shared__ float Bs[16][68];
    int m0 = blockIdx.x * 64, n0 = blockIdx.y * 64;
    int tid = threadIdx.x;
    int lr = tid >> 2, lk = tid & 3;
    const float* Arow = A + (size_t)(m0 + lr) * K + lk * 4;
    int bk = tid >> 4, bn = tid & 15;
    const float* Bpos = B + (size_t)bk * N + n0 + bn * 4;
    int tx = tid & 15, ty = tid >> 4;
    float acc[4][4] = {};
    float4 av = *(const float4*)(Arow);
    float4 bv = *(const float4*)(Bpos);
    for (int k0 = 0; k0 < K; k0 += 16) {
        As[lk*4+0][lr]=av.x; As[lk*4+1][lr]=av.y; As[lk*4+2][lr]=av.z; As[lk*4+3][lr]=av.w;
        *(float4*)&Bs[bk][bn*4] = bv;
        __syncthreads();
        if (k0 + 16 < K) {
            av = *(const float4*)(Arow + k0 + 16);
            bv = *(const float4*)(Bpos + (size_t)(k0 + 16) * N);
        }
        #pragma unroll
        for (int kk = 0; kk < 16; kk++) {
            float4 a4 = *(const float4*)&As[kk][ty*4];
            float4 b4 = *(const float4*)&Bs[kk][tx*4];
            float a_[4]={a4.x,a4.y,a4.z,a4.w}, b_[4]={b4.x,b4.y,b4.z,b4.w};
            #pragma unroll
            for (int i=0;i<4;i++)
                #pragma unroll
                for (int j=0;j<4;j++) acc[i][j] += a_[i]*b_[j];
        }
        __syncthreads();
    }
    #pragma unroll
    for (int i=0;i<4;i++) {
        int m = m0 + ty*4 + i;
        #pragma unroll
        for (int j=0;j<4;j++) g_Wc[(size_t)m*N + n0 + tx*4 + j] = acc[i][j];
    }
}

// NT GEMM. mode 0: g_xin = wte[idx] @ Wc^T + b_ih + b_hh   (M=2048,N=2048,K=256)
//          mode 1: g_L   = g_states_bt @ g_Whcat^T          (M=2048,N=450, K=2048)
__global__ __launch_bounds__(256) void gemm_nt(int mode, const float* __restrict__ Aext,
                                               const int* __restrict__ gather,
                                               const float* __restrict__ bias1,
                                               const float* __restrict__ bias2,
                                               int N, int K) {
    const float *A, *B; float* C;
    if (mode == 0) { A = Aext;        B = g_Wc;    C = g_xin; }
    else           { A = g_states_bt; B = g_Whcat; C = g_L;   }
    __shared__ float As[16][68];
    __shared__ float Bs[16][68];
    int m0 = blockIdx.x * 64, n0 = blockIdx.y * 64;
    int tid = threadIdx.x;
    int lr = tid >> 2, lk = tid & 3;
    int am = m0 + lr;
    int arow = gather ? gather[am] : am;
    const float* Arow = A + (size_t)arow * K + lk * 4;
    int bn = n0 + lr;
    bool bvalid = (bn < N);
    const float* Brow = B + (size_t)(bvalid ? bn : 0) * K + lk * 4;
    int tx = tid & 15, ty = tid >> 4;
    float acc[4][4] = {};
    float4 av = *(const float4*)(Arow);
    float4 bv = bvalid ? *(const float4*)(Brow) : make_float4(0,0,0,0);
    for (int k0 = 0; k0 < K; k0 += 16) {
        As[lk*4+0][lr]=av.x; As[lk*4+1][lr]=av.y; As[lk*4+2][lr]=av.z; As[lk*4+3][lr]=av.w;
        Bs[lk*4+0][lr]=bv.x; Bs[lk*4+1][lr]=bv.y; Bs[lk*4+2][lr]=bv.z; Bs[lk*4+3][lr]=bv.w;
        __syncthreads();
        if (k0 + 16 < K) {
            av = *(const float4*)(Arow + k0 + 16);
            bv = bvalid ? *(const float4*)(Brow + k0 + 16) : make_float4(0,0,0,0);
        }
        #pragma unroll
        for (int kk = 0; kk < 16; kk++) {
            float4 a4 = *(const float4*)&As[kk][ty*4];
            float4 b4 = *(const float4*)&Bs[kk][tx*4];
            float a_[4]={a4.x,a4.y,a4.z,a4.w}, b_[4]={b4.x,b4.y,b4.z,b4.w};
            #pragma unroll
            for (int i=0;i<4;i++)
                #pragma unroll
                for (int j=0;j<4;j++) acc[i][j] += a_[i]*b_[j];
        }
        __syncthreads();
    }
    #pragma unroll
    for (int i=0;i<4;i++) {
        int m = m0 + ty*4 + i;
        #pragma unroll
        for (int j=0;j<4;j++) {
            int n = n0 + tx*4 + j;
            if (n < N) {
                float bb = acc[i][j];
                if (bias1) bb += bias1[n];
                if (bias2) bb += bias2[n];
                C[(size_t)m*N + n] = bb;
            }
        }
    }
}

// persistent recurrence: 128 CTAs x 256 thr, W slice in SMEM, global barrier/step
__global__ __launch_bounds__(256, 1) void recurrence_kernel(const float* __restrict__ Whh) {
    extern __shared__ float sm[];
    float* Ws  = sm;                      // ROWS_REC*RES
    float* Hs  = Ws + ROWS_REC * RES;     // BATCH*RES
    float* red = Hs + BATCH * RES;        // 8*16
    const int tid = threadIdx.x, cta = blockIdx.x;
    const int row0 = cta * ROWS_REC;
    {
        const float4* Wsrc = (const float4*)(Whh + (size_t)row0 * RES);
        float4* Wdst = (float4*)Ws;
        for (int i = tid; i < ROWS_REC*RES/4; i += 256) Wdst[i] = Wsrc[i];
        float4* H4 = (float4*)Hs;
        for (int i = tid; i < BATCH*RES/4; i += 256) H4[i] = make_float4(0,0,0,0);
    }
    __syncthreads();
    const int g = tid >> 6, c = tid & 63;
    const int lane = tid & 31, warp = tid >> 5;
    const float4* Wr[4]; const float4* Hb[4];
    #pragma unroll
    for (int i=0;i<4;i++) Wr[i] = (const float4*)(Ws + (g*4+i)*RES);
    #pragma unroll
    for (int j=0;j<4;j++) Hb[j] = (const float4*)(Hs + j*RES);
    const int rloc = tid >> 2, bidx = tid & 3;

    for (int t = 0; t < TLEN; t++) {
        float xv = 0.f;
        if (tid < 64) xv = g_xin[((size_t)(bidx*TLEN + t))*RES + row0 + rloc];
        float acc[4][4] = {};
        #pragma unroll 8
        for (int q = c; q < RES/4; q += 64) {
            float4 w[4], hh[4];
            #pragma unroll
            for (int i=0;i<4;i++) w[i] = Wr[i][q];
            #pragma unroll
            for (int j=0;j<4;j++) hh[j] = Hb[j][q];
            #pragma unroll
            for (int i=0;i<4;i++)
                #pragma unroll
                for (int j=0;j<4;j++) {
                    acc[i][j] += w[i].x*hh[j].x; acc[i][j] += w[i].y*hh[j].y;
                    acc[i][j] += w[i].z*hh[j].z; acc[i][j] += w[i].w*hh[j].w;
                }
        }
        #pragma unroll
        for (int i=0;i<4;i++)
            #pragma unroll
            for (int j=0;j<4;j++)
                #pragma unroll
                for (int off=16; off; off>>=1)
                    acc[i][j] += __shfl_xor_sync(0xffffffffu, acc[i][j], off);
        if (lane == 0) {
            #pragma unroll
            for (int i=0;i<4;i++)
                #pragma unroll
                for (int j=0;j<4;j++) red[warp*16 + i*4 + j] = acc[i][j];
        }
        __syncthreads();
        if (tid < 64) {
            int gg = rloc >> 2, idx = (rloc & 3)*4 + bidx;
            float y = red[(gg*2)*16 + idx] + red[(gg*2+1)*16 + idx] + xv;
            float hv = tanhf(y);
            int s = row0 + rloc;
            g_states_tb[((size_t)t*BATCH + bidx)*RES + s] = hv;
            g_states_bt[((size_t)(bidx*TLEN + t))*RES + s] = hv;
            __threadfence();
        }
        __syncthreads();
        if (tid == 0) {
            atomicAdd(&g_cnt[t], 1u);
            while (ld_acq(&g_cnt[t]) < (unsigned)NCTA_REC) { }
        }
        __syncthreads();
        {
            const float4* hsrc = (const float4*)(g_states_tb + (size_t)t*BATCH*RES);
            float4* H4 = (float4*)Hs;
            for (int i = tid; i < BATCH*RES/4; i += 256) H4[i] = hsrc[i];
        }
        __syncthreads();
    }
}

__global__ __launch_bounds__(256) void head_out_kernel(const int* __restrict__ targets,
                                                       float* __restrict__ out) {
    __shared__ float lp[NHEAD2];
    __shared__ float rmax[8], rsum[8];
    const int tok = blockIdx.x, tid = threadIdx.x;
    const int lane = tid & 31, warp = tid >> 5;
    const float* Lrow = g_L + (size_t)tok * NHEAD2;
    for (int h = 0; h < 2; h++) {
        float v = (tid < SQV) ? Lrow[h*SQV + tid] : -3.4e38f;
        float m = v;
        #pragma unroll
        for (int off=16; off; off>>=1) m = fmaxf(m, __shfl_xor_sync(0xffffffffu, m, off));
        if (lane == 0) rmax[warp] = m;
        __syncthreads();
        float mx = fmaxf(fmaxf(fmaxf(rmax[0],rmax[1]),fmaxf(rmax[2],rmax[3])),
                         fmaxf(fmaxf(rmax[4],rmax[5]),fmaxf(rmax[6],rmax[7])));
        float e = (tid < SQV) ? expf(v - mx) : 0.f;
        float s = e;
        #pragma unroll
        for (int off=16; off; off>>=1) s += __shfl_xor_sync(0xffffffffu, s, off);
        if (lane == 0) rsum[warp] = s;
        __syncthreads();
        float st = rsum[0]+rsum[1]+rsum[2]+rsum[3]+rsum[4]+rsum[5]+rsum[6]+rsum[7];
        float lse = mx + logf(st);
        if (tid < SQV) lp[h*SQV + tid] = v - lse;
        __syncthreads();
    }
    if (tid == 0) {
        int tg = targets[tok];
        if (tg != -1) {
            int r = tg / SQV, c0 = tg - r*SQV;
            atomicAdd(&g_loss_acc, -(lp[r] + lp[SQV + c0]));
            atomicAdd(&g_mask_cnt, 1);
        }
    }
    size_t base = (size_t)tok * VOCAB;
    for (int i = tid; i < VOCAB; i += 256) {
        int r = i / SQV, c0 = i - r*SQV;
        out[base + i] = lp[r] + lp[SQV + c0];
    }
}

__global__ void finalize_kernel(float* __restrict__ out, size_t out_sz) {
    int i = blockIdx.x * blockDim.x + threadIdx.x;
    size_t need = LOGITS_N + 1 + (size_t)BATCH*RES;
    if (out_sz < need) return;
    if (i == 0) {
        int cnt = g_mask_cnt; if (cnt < 1) cnt = 1;
        out[LOGITS_N] = g_loss_acc / (float)cnt;
    }
    if (i < BATCH*RES) {
        int b = i / RES, r = i - b*RES;
        out[LOGITS_N + 1 + i] = g_states_bt[((size_t)(b*TLEN + TLEN-1))*RES + r];
    }
}

extern "C" void kernel_launch(void* const* d_in, const int* in_sizes, int n_in,
                              void* d_out, int out_size) {
    const int*   idx     = (const int*)  d_in[0];
    const int*   targets = (const int*)  d_in[1];
    const float* wte     = (const float*)d_in[2];
    const float* W_in    = (const float*)d_in[3];
    const float* W_ih    = (const float*)d_in[4];
    const float* b_ih    = (const float*)d_in[5];
    const float* W_hh    = (const float*)d_in[6];
    const float* b_hh    = (const float*)d_in[7];
    const float* Wh1     = (const float*)d_in[8];
    const float* Wh2     = (const float*)d_in[9];
    float* out = (float*)d_out;

    static int smem_set = 0;
    int rec_smem = (ROWS_REC*RES + BATCH*RES + 128) * sizeof(float);
    if (!smem_set) {
        cudaFuncSetAttribute(recurrence_kernel,
                             cudaFuncAttributeMaxDynamicSharedMemorySize, rec_smem);
        smem_set = 1;
    }

    prep_kernel<<<1024, 256>>>(Wh1, Wh2);
    gemm_nn_wc<<<dim3(RES/64, EMBED/64), 256>>>(W_ih, W_in);
    gemm_nt<<<dim3(NTOK/64, RES/64), 256>>>(0, wte, idx, b_ih, b_hh, RES, EMBED);
    recurrence_kernel<<<NCTA_REC, 256, rec_smem>>>(W_hh);
    gemm_nt<<<dim3(NTOK/64, (NHEAD2+63)/64), 256>>>(1, nullptr, nullptr, nullptr, nullptr, NHEAD2, RES);
    head_out_kernel<<<NTOK, 256>>>(targets, out);
    finalize_kernel<<<(BATCH*RES+256)/256 + 1, 256>>>(out, (size_t)out_size);
}

// round 3
// speedup vs baseline: 1.0010x; 1.0010x over previous
#include <cuda_runtime.h>
#include <cuda_bf16.h>
#include <math.h>

#define RES    2048
#define EMBED  256
#define TLEN   512
#define BATCH  4
#define NTOK   (BATCH*TLEN)
#define SQV    225
#define NHEAD2 450
#define VOCAB  50257
#define NCTA_REC 128
#define ROWS_REC 16

static const size_t LOGITS_N = (size_t)NTOK * VOCAB;

__device__ float    g_Wc[RES * EMBED];
__device__ float    g_xin[(size_t)NTOK * RES];
__device__ float    g_states_tb[(size_t)TLEN * BATCH * RES];
__device__ float    g_states_bt[(size_t)NTOK * RES];
__device__ float    g_L[(size_t)NTOK * NHEAD2];
__device__ float    g_Whcat[NHEAD2 * RES];
__device__ unsigned g_cnt[TLEN];
__device__ float    g_loss_acc;
__device__ int      g_mask_cnt;

__device__ __forceinline__ unsigned ld_acq(const unsigned* p) {
    unsigned v;
    asm volatile("ld.acquire.gpu.u32 %0, [%1];" : "=r"(v) : "l"(p) : "memory");
    return v;
}

// packed dual-FMA: d(f32x2) += a(f32x2) * b(f32x2)
__device__ __forceinline__ void ffma2(unsigned long long& d,
                                      unsigned long long a,
                                      unsigned long long b) {
    asm("fma.rn.f32x2 %0, %1, %2, %0;" : "+l"(d) : "l"(a), "l"(b));
}

__global__ void prep_kernel(const float* __restrict__ Wh1, const float* __restrict__ Wh2) {
    int i0 = blockIdx.x * blockDim.x + threadIdx.x;
    int stride = gridDim.x * blockDim.x;
    for (int j = i0; j < NHEAD2 * RES; j += stride) {
        int v = j / RES, r = j - v * RES;
        g_Whcat[j] = (v < SQV) ? Wh1[v * RES + r] : Wh2[(v - SQV) * RES + r];
    }
    if (i0 < TLEN) g_cnt[i0] = 0u;
    if (i0 == 0) { g_loss_acc = 0.f; g_mask_cnt = 0; }
}

// Wc = W_ih[2048x2048] @ W_in[2048x256]   (NN GEMM)
__global__ __launch_bounds__(256) void gemm_nn_wc(const float* __restrict__ A,
                                                  const float* __restrict__ B) {
    const int N = EMBED, K = RES;
    __shared__ float As[16][68];
    __shared__ float Bs[16][68];
    int m0 = blockIdx.x * 64, n0 = blockIdx.y * 64;
    int tid = threadIdx.x;
    int lr = tid >> 2, lk = tid & 3;
    const float* Arow = A + (size_t)(m0 + lr) * K + lk * 4;
    int bk = tid >> 4, bn = tid & 15;
    const float* Bpos = B + (size_t)bk * N + n0 + bn * 4;
    int tx = tid & 15, ty = tid >> 4;
    float acc[4][4] = {};
    float4 av = *(const float4*)(Arow);
    float4 bv = *(const float4*)(Bpos);
    for (int k0 = 0; k0 < K; k0 += 16) {
        As[lk*4+0][lr]=av.x; As[lk*4+1][lr]=av.y; As[lk*4+2][lr]=av.z; As[lk*4+3][lr]=av.w;
        *(float4*)&Bs[bk][bn*4] = bv;
        __syncthreads();
        if (k0 + 16 < K) {
            av = *(const float4*)(Arow + k0 + 16);
            bv = *(const float4*)(Bpos + (size_t)(k0 + 16) * N);
        }
        #pragma unroll
        for (int kk = 0; kk < 16; kk++) {
            float4 a4 = *(const float4*)&As[kk][ty*4];
            float4 b4 = *(const float4*)&Bs[kk][tx*4];
            float a_[4]={a4.x,a4.y,a4.z,a4.w}, b_[4]={b4.x,b4.y,b4.z,b4.w};
            #pragma unroll
            for (int i=0;i<4;i++)
                #pragma unroll
                for (int j=0;j<4;j++) acc[i][j] += a_[i]*b_[j];
        }
        __syncthreads();
    }
    #pragma unroll
    for (int i=0;i<4;i++) {
        int m = m0 + ty*4 + i;
        #pragma unroll
        for (int j=0;j<4;j++) g_Wc[(size_t)m*N + n0 + tx*4 + j] = acc[i][j];
    }
}

// NT GEMM. mode 0: g_xin = wte[idx] @ Wc^T + b_ih + b_hh   (M=2048,N=2048,K=256)
//          mode 1: g_L   = g_states_bt @ g_Whcat^T          (M=2048,N=450, K=2048)
__global__ __launch_bounds__(256) void gemm_nt(int mode, const float* __restrict__ Aext,
                                               const int* __restrict__ gather,
                                               const float* __restrict__ bias1,
                                               const float* __restrict__ bias2,
                                               int N, int K) {
    const float *A, *B; float* C;
    if (mode == 0) { A = Aext;        B = g_Wc;    C = g_xin; }
    else           { A = g_states_bt; B = g_Whcat; C = g_L;   }
    __shared__ float As[16][68];
    __shared__ float Bs[16][68];
    int m0 = blockIdx.x * 64, n0 = blockIdx.y * 64;
    int tid = threadIdx.x;
    int lr = tid >> 2, lk = tid & 3;
    int am = m0 + lr;
    int arow = gather ? gather[am] : am;
    const float* Arow = A + (size_t)arow * K + lk * 4;
    int bn = n0 + lr;
    bool bvalid = (bn < N);
    const float* Brow = B + (size_t)(bvalid ? bn : 0) * K + lk * 4;
    int tx = tid & 15, ty = tid >> 4;
    float acc[4][4] = {};
    float4 av = *(const float4*)(Arow);
    float4 bv = bvalid ? *(const float4*)(Brow) : make_float4(0,0,0,0);
    for (int k0 = 0; k0 < K; k0 += 16) {
        As[lk*4+0][lr]=av.x; As[lk*4+1][lr]=av.y; As[lk*4+2][lr]=av.z; As[lk*4+3][lr]=av.w;
        Bs[lk*4+0][lr]=bv.x; Bs[lk*4+1][lr]=bv.y; Bs[lk*4+2][lr]=bv.z; Bs[lk*4+3][lr]=bv.w;
        __syncthreads();
        if (k0 + 16 < K) {
            av = *(const float4*)(Arow + k0 + 16);
            bv = bvalid ? *(const float4*)(Brow + k0 + 16) : make_float4(0,0,0,0);
        }
        #pragma unroll
        for (int kk = 0; kk < 16; kk++) {
            float4 a4 = *(const float4*)&As[kk][ty*4];
            float4 b4 = *(const float4*)&Bs[kk][tx*4];
            float a_[4]={a4.x,a4.y,a4.z,a4.w}, b_[4]={b4.x,b4.y,b4.z,b4.w};
            #pragma unroll
            for (int i=0;i<4;i++)
                #pragma unroll
                for (int j=0;j<4;j++) acc[i][j] += a_[i]*b_[j];
        }
        __syncthreads();
    }
    #pragma unroll
    for (int i=0;i<4;i++) {
        int m = m0 + ty*4 + i;
        #pragma unroll
        for (int j=0;j<4;j++) {
            int n = n0 + tx*4 + j;
            if (n < N) {
                float bb = acc[i][j];
                if (bias1) bb += bias1[n];
                if (bias2) bb += bias2[n];
                C[(size_t)m*N + n] = bb;
            }
        }
    }
}

// Persistent recurrence v2: 128 CTAs x 512 thr.
// W_hh resident in registers (4 rows x 16 k per thread), h streamed from SMEM
// with 4-way lane broadcast, packed f32x2 FMAs, global software barrier/step.
__global__ __launch_bounds__(512, 1) void recurrence_kernel(const float* __restrict__ Whh) {
    extern __shared__ float sm[];
    float* Hs  = sm;                 // [4][RES]  (b-major)
    float* red = Hs + 4 * RES;       // [16][68]
    const int tid = threadIdx.x, cta = blockIdx.x;
    const int row0 = cta * ROWS_REC;
    const int g = tid & 3;           // row group (4 rows)
    const int c = tid >> 2;          // k-slice index: k in [c*16, c*16+16)
    const int lane = tid & 31, warp = tid >> 5;

    // W slice -> registers (held for all 512 steps): rows row0+g*4+i, 16 k as 8 f32x2
    ulonglong2 wr[4][4];
    #pragma unroll
    for (int i = 0; i < 4; i++) {
        const ulonglong2* p = (const ulonglong2*)(Whh + (size_t)(row0 + g*4 + i) * RES + c*16);
        #pragma unroll
        for (int kq = 0; kq < 4; kq++) wr[i][kq] = p[kq];
    }
    // h0 = 0
    for (int i = tid; i < 4*RES/4; i += 512) ((float4*)Hs)[i] = make_float4(0,0,0,0);
    __syncthreads();

    const int ob = tid & 3, orow = tid >> 2;   // output mapping for tid<64

    for (int t = 0; t < TLEN; t++) {
        float xv = 0.f;
        if (tid < 64) xv = g_xin[((size_t)(ob*TLEN + t))*RES + row0 + orow];

        unsigned long long acc2[4][4];
        #pragma unroll
        for (int i = 0; i < 4; i++)
            #pragma unroll
            for (int j = 0; j < 4; j++) acc2[i][j] = 0ULL;

        const ulonglong2* HsB = (const ulonglong2*)Hs;   // [b*(RES/4) + q] (16B units)
        #pragma unroll
        for (int kq = 0; kq < 4; kq++) {
            #pragma unroll
            for (int b = 0; b < 4; b++) {
                ulonglong2 hp = HsB[b*(RES/4) + c*4 + kq];
                #pragma unroll
                for (int i = 0; i < 4; i++) {
                    ffma2(acc2[i][b], wr[i][kq].x, hp.x);
                    ffma2(acc2[i][b], wr[i][kq].y, hp.y);
                }
            }
        }
        // collapse k-pairs
        float accs[4][4];
        #pragma unroll
        for (int i = 0; i < 4; i++)
            #pragma unroll
            for (int j = 0; j < 4; j++) {
                float2 f = *reinterpret_cast<float2*>(&acc2[i][j]);
                accs[i][j] = f.x + f.y;
            }
        // butterfly over c_local (lane bits 2..4); lanes with same g only
        #pragma unroll
        for (int i = 0; i < 4; i++)
            #pragma unroll
            for (int j = 0; j < 4; j++) {
                accs[i][j] += __shfl_xor_sync(0xffffffffu, accs[i][j], 4);
                accs[i][j] += __shfl_xor_sync(0xffffffffu, accs[i][j], 8);
                accs[i][j] += __shfl_xor_sync(0xffffffffu, accs[i][j], 16);
            }
        if (lane < 4) {   // c_local==0, lane==g
            #pragma unroll
            for (int i = 0; i < 4; i++)
                #pragma unroll
                for (int j = 0; j < 4; j++)
                    red[warp*68 + lane*16 + i*4 + j] = accs[i][j];
        }
        __syncthreads();
        if (tid < 64) {
            float y = xv;
            #pragma unroll
            for (int w = 0; w < 16; w++) y += red[w*68 + orow*4 + ob];
            float hv = tanhf(y);
            int s = row0 + orow;
            g_states_tb[((size_t)t*BATCH + ob)*RES + s] = hv;
            g_states_bt[((size_t)(ob*TLEN + t))*RES + s] = hv;
            __threadfence();
        }
        __syncthreads();
        if (tid == 0) {
            atomicAdd(&g_cnt[t], 1u);
            while (ld_acq(&g_cnt[t]) < (unsigned)NCTA_REC) { }
        }
        __syncthreads();
        // broadcast h_t into SMEM (32 KB)
        {
            const float4* hsrc = (const float4*)(g_states_tb + (size_t)t*BATCH*RES);
            for (int i = tid; i < 4*RES/4; i += 512) ((float4*)Hs)[i] = hsrc[i];
        }
        __syncthreads();
    }
}

__global__ __launch_bounds__(256) void head_out_kernel(const int* __restrict__ targets,
                                                       float* __restrict__ out) {
    __shared__ float lp[NHEAD2];
    __shared__ float rmax[8], rsum[8];
    const int tok = blockIdx.x, tid = threadIdx.x;
    const int lane = tid & 31, warp = tid >> 5;
    const float* Lrow = g_L + (size_t)tok * NHEAD2;
    for (int h = 0; h < 2; h++) {
        float v = (tid < SQV) ? Lrow[h*SQV + tid] : -3.4e38f;
        float m = v;
        #pragma unroll
        for (int off=16; off; off>>=1) m = fmaxf(m, __shfl_xor_sync(0xffffffffu, m, off));
        if (lane == 0) rmax[warp] = m;
        __syncthreads();
        float mx = fmaxf(fmaxf(fmaxf(rmax[0],rmax[1]),fmaxf(rmax[2],rmax[3])),
                         fmaxf(fmaxf(rmax[4],rmax[5]),fmaxf(rmax[6],rmax[7])));
        float e = (tid < SQV) ? expf(v - mx) : 0.f;
        float s = e;
        #pragma unroll
        for (int off=16; off; off>>=1) s += __shfl_xor_sync(0xffffffffu, s, off);
        if (lane == 0) rsum[warp] = s;
        __syncthreads();
        float st = rsum[0]+rsum[1]+rsum[2]+rsum[3]+rsum[4]+rsum[5]+rsum[6]+rsum[7];
        float lse = mx + logf(st);
        if (tid < SQV) lp[h*SQV + tid] = v - lse;
        __syncthreads();
    }
    if (tid == 0) {
        int tg = targets[tok];
        if (tg != -1) {
            int r = tg / SQV, c0 = tg - r*SQV;
            atomicAdd(&g_loss_acc, -(lp[r] + lp[SQV + c0]));
            atomicAdd(&g_mask_cnt, 1);
        }
    }
    size_t base = (size_t)tok * VOCAB;
    for (int i = tid; i < VOCAB; i += 256) {
        int r = i / SQV, c0 = i - r*SQV;
        out[base + i] = lp[r] + lp[SQV + c0];
    }
}

__global__ void finalize_kernel(float* __restrict__ out, size_t out_sz) {
    int i = blockIdx.x * blockDim.x + threadIdx.x;
    size_t need = LOGITS_N + 1 + (size_t)BATCH*RES;
    if (out_sz < need) return;
    if (i == 0) {
        int cnt = g_mask_cnt; if (cnt < 1) cnt = 1;
        out[LOGITS_N] = g_loss_acc / (float)cnt;
    }
    if (i < BATCH*RES) {
        int b = i / RES, r = i - b*RES;
        out[LOGITS_N + 1 + i] = g_states_bt[((size_t)(b*TLEN + TLEN-1))*RES + r];
    }
}

extern "C" void kernel_launch(void* const* d_in, const int* in_sizes, int n_in,
                              void* d_out, int out_size) {
    const int*   idx     = (const int*)  d_in[0];
    const int*   targets = (const int*)  d_in[1];
    const float* wte     = (const float*)d_in[2];
    const float* W_in    = (const float*)d_in[3];
    const float* W_ih    = (const float*)d_in[4];
    const float* b_ih    = (const float*)d_in[5];
    const float* W_hh    = (const float*)d_in[6];
    const float* b_hh    = (const float*)d_in[7];
    const float* Wh1     = (const float*)d_in[8];
    const float* Wh2     = (const float*)d_in[9];
    float* out = (float*)d_out;

    int rec_smem = (4*RES + 16*68) * sizeof(float);   // 37120 B < 48 KB

    prep_kernel<<<1024, 256>>>(Wh1, Wh2);
    gemm_nn_wc<<<dim3(RES/64, EMBED/64), 256>>>(W_ih, W_in);
    gemm_nt<<<dim3(NTOK/64, RES/64), 256>>>(0, wte, idx, b_ih, b_hh, RES, EMBED);
    recurrence_kernel<<<NCTA_REC, 512, rec_smem>>>(W_hh);
    gemm_nt<<<dim3(NTOK/64, (NHEAD2+63)/64), 256>>>(1, nullptr, nullptr, nullptr, nullptr, NHEAD2, RES);
    head_out_kernel<<<NTOK, 256>>>(targets, out);
    finalize_kernel<<<(BATCH*RES+256)/256 + 1, 256>>>(out, (size_t)out_size);
}